// round 10
// baseline (speedup 1.0000x reference)
#include <cuda_runtime.h>
#include <cfloat>
#include <math.h>

#define NMAX   100000
#define HID    128
#define S1     50
#define S2     10
#define TILE   48          // nodes per k2 tile
#define XP     132         // x-buffer stride (floats)
#define WSP    132         // padded weight stride (floats)
#define BT     512         // k2 threads

// ---------------- scratch (static __device__, no allocations) ----------------
__device__ __align__(16) float4 g_featP[NMAX];                 // padded features
__device__ __align__(16) float  g_h1[(size_t)NMAX * HID];      // enc1 output
__device__ float g_scores[NMAX];
__device__ float g_pm[256];
__device__ float g_ps[256];
__device__ float g_MS[2];

typedef unsigned long long ull;

// ---------------- f32x2 helpers ----------------
__device__ __forceinline__ ull pack2f(float a, float b) {
    ull r;
    asm("mov.b64 %0, {%1, %2};" : "=l"(r) : "f"(a), "f"(b));
    return r;
}
__device__ __forceinline__ float2 unpack2f(ull v) {
    float2 r;
    asm("mov.b64 {%0, %1}, %2;" : "=f"(r.x), "=f"(r.y) : "l"(v));
    return r;
}
__device__ __forceinline__ void ffma2(ull& d, ull a, ull b) {
    asm("fma.rn.f32x2 %0, %1, %2, %0;" : "+l"(d) : "l"(a), "l"(b));
}

// Register-blocked GEMM slice: RPT rows x 6 nodes per thread, K=128.
// Wb: first weight row (stride WSP, k-contiguous). xth = xs + tx*XP;
// node j lives at offset j*8*XP. Low register pressure by construction:
// acc (2*RPT*6) + w (4*RPT) + one xp at a time; unroll 2 bounds in-flight loads.
template<int RPT>
__device__ __forceinline__ void gemm6(const float* __restrict__ Wb,
                                      const float* __restrict__ xth,
                                      const float init[RPT], float v[RPT][6]) {
    ull acc[RPT][6];
#pragma unroll
    for (int ro = 0; ro < RPT; ro++) {
        ull ini = pack2f(init[ro], 0.f);
#pragma unroll
        for (int j = 0; j < 6; j++) acc[ro][j] = ini;
    }
#pragma unroll 2
    for (int k = 0; k < 128; k += 4) {
        ulonglong2 w[RPT];
#pragma unroll
        for (int ro = 0; ro < RPT; ro++)
            w[ro] = *(const ulonglong2*)(Wb + ro * WSP + k);
#pragma unroll
        for (int j = 0; j < 6; j++) {
            ulonglong2 xp = *(const ulonglong2*)(xth + j * 8 * XP + k);
#pragma unroll
            for (int ro = 0; ro < RPT; ro++) {
                ffma2(acc[ro][j], xp.x, w[ro].x);
                ffma2(acc[ro][j], xp.y, w[ro].y);
            }
        }
    }
#pragma unroll
    for (int ro = 0; ro < RPT; ro++)
#pragma unroll
        for (int j = 0; j < 6; j++) {
            float2 p = unpack2f(acc[ro][j]);
            v[ro][j] = p.x + p.y;
        }
}

// ---------------- kernel 0: pad features [N,3] -> float4 ----------------
__global__ void k_pad(const float* __restrict__ f, int NN) {
    int i = blockIdx.x * blockDim.x + threadIdx.x;
    if (i < NN) {
        g_featP[i] = make_float4(f[3 * i], f[3 * i + 1], f[3 * i + 2], 0.f);
    }
}

// ---------------- kernel 1: enc1 -> h1, one warp per node ----------------
__global__ void k_enc1(const int* __restrict__ n1, const float* __restrict__ W1, int NN) {
    int node = (blockIdx.x << 3) + (threadIdx.x >> 5);
    int lane = threadIdx.x & 31;
    if (node >= NN) return;
    const int* nb = n1 + (size_t)node * S1;
    float a0, a1, a2;
    {
        int i1 = nb[lane];
        float4 f = g_featP[i1];
        a0 = f.x; a1 = f.y; a2 = f.z;
    }
    if (lane < S1 - 32) {
        int i2 = nb[lane + 32];
        float4 f = g_featP[i2];
        a0 += f.x; a1 += f.y; a2 += f.z;
    }
#pragma unroll
    for (int off = 16; off; off >>= 1) {
        a0 += __shfl_xor_sync(0xffffffffu, a0, off);
        a1 += __shfl_xor_sync(0xffffffffu, a1, off);
        a2 += __shfl_xor_sync(0xffffffffu, a2, off);
    }
    float4 fs = g_featP[node];
    const float inv = 1.f / (float)(S1 + 1);
    a0 = (a0 + fs.x) * inv;
    a1 = (a1 + fs.y) * inv;
    a2 = (a2 + fs.z) * inv;
    const float* w = W1 + lane * 12;     // rows 4*lane .. 4*lane+3
    float4 h;
    h.x = fmaxf(fmaf(a0, w[0], fmaf(a1, w[1],  a2 * w[2])),  0.f);
    h.y = fmaxf(fmaf(a0, w[3], fmaf(a1, w[4],  a2 * w[5])),  0.f);
    h.z = fmaxf(fmaf(a0, w[6], fmaf(a1, w[7],  a2 * w[8])),  0.f);
    h.w = fmaxf(fmaf(a0, w[9], fmaf(a1, w[10], a2 * w[11])), 0.f);
    *(float4*)(g_h1 + (size_t)node * HID + (lane << 2)) = h;
}

// ---------------- kernel 2: enc2 + MLP + scores ----------------
// 512 threads, 48 nodes/tile, 2x6 (and 1x6) register tiles, f32x2 FMA.
__global__ void __launch_bounds__(BT, 1)
k2(const int* __restrict__ nodes, const int* __restrict__ n2,
   const float* __restrict__ W2g, const float* __restrict__ wag,
   const float* __restrict__ bag, const float* __restrict__ wbg,
   const float* __restrict__ bbg, const float* __restrict__ wcg,
   const float* __restrict__ bcg, const int* __restrict__ psp,
   const int* __restrict__ nep, int Nq, int numTiles) {
    extern __shared__ float sh[];
    float* W2s = sh;                       // 128*132
    float* was = W2s + 128 * WSP;          // 128*132
    float* wbs = was + 128 * WSP;          // 64*132
    float* xs  = wbs + 64 * WSP;           // 48*132 node-major
    float* ys  = xs  + TILE * XP;          // 48*132 node-major
    float* red = ys  + TILE * XP;          // 48*17 per-warp score partials
    float* waL = red + TILE * 17;          // 128 (last col of w_a)
    float* wcs = waL + 128;                // 64
    float* bas = wcs + 64;                 // 128
    float* bbs = bas + 128;                // 64

    int tid = threadIdx.x;
    for (int i = tid; i < 128 * 128; i += BT) W2s[(i >> 7) * WSP + (i & 127)] = W2g[i];
    for (int i = tid; i < 128 * 129; i += BT) {
        int r = i / 129, k = i - r * 129;
        if (k < 128) was[r * WSP + k] = wag[i]; else waL[r] = wag[i];
    }
    for (int i = tid; i < 64 * 128; i += BT) wbs[(i >> 7) * WSP + (i & 127)] = wbg[i];
    if (tid < 64)  wcs[tid] = wcg[tid];
    if (tid < 128) bas[tid] = bag[tid];
    if (tid < 64)  bbs[tid] = bbg[tid];
    float rem = (float)(psp[0] - nep[0]);
    float bcv = bcg[0];
    __syncthreads();

    int tx   = tid & 7;         // node group: nodes tx + 8j, j=0..5
    int ty   = tid >> 3;        // row group 0..63
    int lane = tid & 31;
    int wid  = tid >> 5;        // 0..15

    for (int tile = blockIdx.x; tile < numTiles; tile += gridDim.x) {
        int base = tile * TILE;

        // ---- gather agg2: 16 warps x 3 nodes, lane covers 16B of the 512B row
#pragma unroll
        for (int s = 0; s < 3; s++) {
            int nn = wid * 3 + s;
            int node = base + nn;
            float4 acc = make_float4(0.f, 0.f, 0.f, 0.f);
            if (node < Nq) {
                int q = nodes[node];
                acc = *(const float4*)(g_h1 + (size_t)q * HID + (lane << 2));
                const int* nb = n2 + (size_t)q * S2;
#pragma unroll
                for (int jj = 0; jj < S2; jj++) {
                    int qq = nb[jj];
                    float4 u = *(const float4*)(g_h1 + (size_t)qq * HID + (lane << 2));
                    acc.x += u.x; acc.y += u.y; acc.z += u.z; acc.w += u.w;
                }
                const float inv = 1.f / (float)(S2 + 1);
                acc.x *= inv; acc.y *= inv; acc.z *= inv; acc.w *= inv;
            }
            *(float4*)(xs + nn * XP + (lane << 2)) = acc;
        }
        __syncthreads();

        float v[2][6];

        // ---- GEMM1: emb = relu(W2 @ agg2), rows 2ty, 2ty+1
        {
            const float init0[2] = {0.f, 0.f};
            gemm6<2>(W2s + (ty << 1) * WSP, xs + tx * XP, init0, v);
#pragma unroll
            for (int ro = 0; ro < 2; ro++)
#pragma unroll
                for (int j = 0; j < 6; j++)
                    ys[(tx + 8 * j) * XP + (ty << 1) + ro] = fmaxf(v[ro][j], 0.f);
        }
        __syncthreads();

        // ---- GEMM2: ya = relu(w_a @ [emb; rem] + b_a) -> xs
        {
            float init[2];
#pragma unroll
            for (int ro = 0; ro < 2; ro++) {
                int r = (ty << 1) + ro;
                init[ro] = bas[r] + waL[r] * rem;
            }
            gemm6<2>(was + (ty << 1) * WSP, ys + tx * XP, init, v);
#pragma unroll
            for (int ro = 0; ro < 2; ro++)
#pragma unroll
                for (int j = 0; j < 6; j++)
                    xs[(tx + 8 * j) * XP + (ty << 1) + ro] = fmaxf(v[ro][j], 0.f);
        }
        __syncthreads();

        // ---- GEMM3 + wc dot: row ty of w_b, warp-shuffle reduce over ty-subgroup
        {
            const float init0[1] = {0.f};
            float v3[1][6];
            gemm6<1>(wbs + ty * WSP, xs + tx * XP, init0, v3);
            float wcv = wcs[ty], bbv = bbs[ty];
            float c[6];
#pragma unroll
            for (int j = 0; j < 6; j++)
                c[j] = wcv * fmaxf(v3[0][j] + bbv, 0.f);
            // lane = 8p + tx (p = ty&3): reduce over p via xor 8, 16
#pragma unroll
            for (int off = 8; off <= 16; off <<= 1)
#pragma unroll
                for (int j = 0; j < 6; j++)
                    c[j] += __shfl_xor_sync(0xffffffffu, c[j], off);
            if (lane < 8) {
#pragma unroll
                for (int j = 0; j < 6; j++)
                    red[(tx + 8 * j) * 17 + wid] = c[j];
            }
        }
        __syncthreads();

        if (tid < TILE) {
            float s = bcv;
#pragma unroll
            for (int t = 0; t < 16; t++) s += red[tid * 17 + t];
            int node = base + tid;
            if (node < Nq) g_scores[node] = s;
        }
        // no extra sync: red is next written only after 3 more barriers
    }
}

// ---------------- softmax (online max+sumexp) ----------------
__device__ __forceinline__ void sm_comb(float& m, float& s, float mo, float so) {
    if (mo > m) { float t = m; m = mo; mo = t; t = s; s = so; so = t; }
    if (so != 0.f) s += so * expf(mo - m);
}

__global__ void k_red1(int N) {
    float m = -FLT_MAX, s = 0.f;
    for (int i = blockIdx.x * blockDim.x + threadIdx.x; i < N; i += gridDim.x * blockDim.x) {
        float x = g_scores[i];
        if (x > m) { s = s * expf(m - x) + 1.f; m = x; }
        else        s += expf(x - m);
    }
#pragma unroll
    for (int off = 16; off; off >>= 1) {
        float mo = __shfl_xor_sync(0xffffffffu, m, off);
        float so = __shfl_xor_sync(0xffffffffu, s, off);
        sm_comb(m, s, mo, so);
    }
    __shared__ float shm[8], shs[8];
    int lane = threadIdx.x & 31, wid = threadIdx.x >> 5;
    if (lane == 0) { shm[wid] = m; shs[wid] = s; }
    __syncthreads();
    if (threadIdx.x < 32) {
        float m2 = (lane < 8) ? shm[lane] : -FLT_MAX;
        float s2 = (lane < 8) ? shs[lane] : 0.f;
#pragma unroll
        for (int off = 4; off; off >>= 1) {
            float mo = __shfl_xor_sync(0xffffffffu, m2, off);
            float so = __shfl_xor_sync(0xffffffffu, s2, off);
            sm_comb(m2, s2, mo, so);
        }
        if (threadIdx.x == 0) { g_pm[blockIdx.x] = m2; g_ps[blockIdx.x] = s2; }
    }
}

__global__ void k_red2(int RB) {
    int t = threadIdx.x;
    float m = (t < RB) ? g_pm[t] : -FLT_MAX;
    float s = (t < RB) ? g_ps[t] : 0.f;
#pragma unroll
    for (int off = 16; off; off >>= 1) {
        float mo = __shfl_xor_sync(0xffffffffu, m, off);
        float so = __shfl_xor_sync(0xffffffffu, s, off);
        sm_comb(m, s, mo, so);
    }
    __shared__ float shm[8], shs[8];
    int lane = t & 31, wid = t >> 5;
    if (lane == 0) { shm[wid] = m; shs[wid] = s; }
    __syncthreads();
    if (t < 32) {
        float m2 = (lane < 8) ? shm[lane] : -FLT_MAX;
        float s2 = (lane < 8) ? shs[lane] : 0.f;
#pragma unroll
        for (int off = 4; off; off >>= 1) {
            float mo = __shfl_xor_sync(0xffffffffu, m2, off);
            float so = __shfl_xor_sync(0xffffffffu, s2, off);
            sm_comb(m2, s2, mo, so);
        }
        if (t == 0) { g_MS[0] = m2; g_MS[1] = 1.f / s2; }
    }
}

__global__ void k_norm(float* __restrict__ out, int N) {
    int i = blockIdx.x * blockDim.x + threadIdx.x;
    if (i < N) out[i] = expf(g_scores[i] - g_MS[0]) * g_MS[1];
}

// ---------------- launch ----------------
static const int SMEM2 = (128 * WSP + 128 * WSP + 64 * WSP + TILE * XP + TILE * XP
                          + TILE * 17 + 128 + 64 + 128 + 64) * (int)sizeof(float);

extern "C" void kernel_launch(void* const* d_in, const int* in_sizes, int n_in,
                              void* d_out, int out_size) {
    const int*   nodes = (const int*)d_in[0];
    const float* feat  = (const float*)d_in[1];
    const int*   n1    = (const int*)d_in[2];
    const int*   n2    = (const int*)d_in[3];
    const float* W1    = (const float*)d_in[4];
    const float* W2    = (const float*)d_in[5];
    const float* wa    = (const float*)d_in[6];
    const float* ba    = (const float*)d_in[7];
    const float* wb    = (const float*)d_in[8];
    const float* bb    = (const float*)d_in[9];
    const float* wc    = (const float*)d_in[10];
    const float* bc    = (const float*)d_in[11];
    const int*   ps    = (const int*)d_in[12];
    const int*   ne    = (const int*)d_in[13];

    int Nq = in_sizes[0];
    int NN = in_sizes[1] / 3;

    cudaFuncSetAttribute(k2, cudaFuncAttributeMaxDynamicSharedMemorySize, SMEM2);

    k_pad<<<(NN + 255) / 256, 256>>>(feat, NN);
    k_enc1<<<(NN + 7) / 8, 256>>>(n1, W1, NN);

    int numTiles = (Nq + TILE - 1) / TILE;
    k2<<<152, BT, SMEM2>>>(nodes, n2, W2, wa, ba, wb, bb, wc, bc, ps, ne, Nq, numTiles);

    k_red1<<<240, 256>>>(Nq);
    k_red2<<<1, 256>>>(240);
    k_norm<<<(Nq + 255) / 256, 256>>>((float*)d_out, Nq);
}

// round 11
// speedup vs baseline: 2.0378x; 2.0378x over previous
#include <cuda_runtime.h>
#include <cfloat>
#include <math.h>

#define NMAX   100000
#define HID    128
#define S1     50
#define S2     10
#define TILE   64          // nodes per k2 tile (8 per warp)
#define XP     128         // x-buffer stride (floats)
#define BT     256         // k2 threads

// ---------------- scratch (static __device__, no allocations) ----------------
__device__ __align__(16) float4 g_featP[NMAX];                 // padded features
__device__ __align__(16) float  g_h1[(size_t)NMAX * HID];      // enc1 output
__device__ float g_scores[NMAX];
__device__ float g_pm[256];
__device__ float g_ps[256];
__device__ float g_MS[2];

typedef unsigned long long ull;

// ---------------- f32x2 helpers ----------------
__device__ __forceinline__ ull pack2f(float a, float b) {
    ull r;
    asm("mov.b64 %0, {%1, %2};" : "=l"(r) : "f"(a), "f"(b));
    return r;
}
__device__ __forceinline__ float2 unpack2f(ull v) {
    float2 r;
    asm("mov.b64 {%0, %1}, %2;" : "=f"(r.x), "=f"(r.y) : "l"(v));
    return r;
}
__device__ __forceinline__ void ffma2(ull& d, ull a, ull b) {
    asm("fma.rn.f32x2 %0, %1, %2, %0;" : "+l"(d) : "l"(a), "l"(b));
}

// swizzled weight index: element (r,k) lives at r*128 + ((k4 ^ (r&7))<<2) + (k&3)
__device__ __forceinline__ int wswz(int r, int k) {
    return (r << 7) + ((((k >> 2) ^ (r & 7)) << 2)) + (k & 3);
}

// GEMM slice: RPT rows (lane + 32*ro) x 8 nodes per warp, K=128.
// Wt = weight base + lane*128 (swizzled layout, row stride 32*128 per ro).
// xnb = xs + jb*XP: 8 node rows, k-contiguous; loads are warp-broadcast.
template<int RPT>
__device__ __forceinline__ void gemmSw(const float* __restrict__ Wt,
                                       const float* __restrict__ xnb,
                                       int rx7, const float init[RPT],
                                       float v[RPT][8]) {
    ull acc[RPT][8];
#pragma unroll
    for (int ro = 0; ro < RPT; ro++) {
        ull ini = pack2f(init[ro], 0.f);
#pragma unroll
        for (int j = 0; j < 8; j++) acc[ro][j] = ini;
    }
#pragma unroll 2
    for (int k4 = 0; k4 < 32; k4++) {
        int soff = ((k4 ^ rx7) << 2);
        ulonglong2 w[RPT];
#pragma unroll
        for (int ro = 0; ro < RPT; ro++)
            w[ro] = *(const ulonglong2*)(Wt + (ro << 12) + soff);   // ro*32*128
#pragma unroll
        for (int j = 0; j < 8; j++) {
            ulonglong2 xp = *(const ulonglong2*)(xnb + j * XP + (k4 << 2));
#pragma unroll
            for (int ro = 0; ro < RPT; ro++) {
                ffma2(acc[ro][j], xp.x, w[ro].x);
                ffma2(acc[ro][j], xp.y, w[ro].y);
            }
        }
    }
#pragma unroll
    for (int ro = 0; ro < RPT; ro++)
#pragma unroll
        for (int j = 0; j < 8; j++) {
            float2 p = unpack2f(acc[ro][j]);
            v[ro][j] = p.x + p.y;
        }
}

// ---------------- kernel 0: pad features [N,3] -> float4 ----------------
__global__ void k_pad(const float* __restrict__ f, int NN) {
    int i = blockIdx.x * blockDim.x + threadIdx.x;
    if (i < NN) {
        g_featP[i] = make_float4(f[3 * i], f[3 * i + 1], f[3 * i + 2], 0.f);
    }
}

// ---------------- kernel 1: enc1 -> h1, one warp per node ----------------
__global__ void k_enc1(const int* __restrict__ n1, const float* __restrict__ W1, int NN) {
    int node = (blockIdx.x << 3) + (threadIdx.x >> 5);
    int lane = threadIdx.x & 31;
    if (node >= NN) return;
    const int* nb = n1 + (size_t)node * S1;
    float a0, a1, a2;
    {
        int i1 = nb[lane];
        float4 f = g_featP[i1];
        a0 = f.x; a1 = f.y; a2 = f.z;
    }
    if (lane < S1 - 32) {
        int i2 = nb[lane + 32];
        float4 f = g_featP[i2];
        a0 += f.x; a1 += f.y; a2 += f.z;
    }
#pragma unroll
    for (int off = 16; off; off >>= 1) {
        a0 += __shfl_xor_sync(0xffffffffu, a0, off);
        a1 += __shfl_xor_sync(0xffffffffu, a1, off);
        a2 += __shfl_xor_sync(0xffffffffu, a2, off);
    }
    float4 fs = g_featP[node];
    const float inv = 1.f / (float)(S1 + 1);
    a0 = (a0 + fs.x) * inv;
    a1 = (a1 + fs.y) * inv;
    a2 = (a2 + fs.z) * inv;
    const float* w = W1 + lane * 12;     // rows 4*lane .. 4*lane+3
    float4 h;
    h.x = fmaxf(fmaf(a0, w[0], fmaf(a1, w[1],  a2 * w[2])),  0.f);
    h.y = fmaxf(fmaf(a0, w[3], fmaf(a1, w[4],  a2 * w[5])),  0.f);
    h.z = fmaxf(fmaf(a0, w[6], fmaf(a1, w[7],  a2 * w[8])),  0.f);
    h.w = fmaxf(fmaf(a0, w[9], fmaf(a1, w[10], a2 * w[11])), 0.f);
    *(float4*)(g_h1 + (size_t)node * HID + (lane << 2)) = h;
}

// ---------------- kernel 2: enc2 + MLP + scores ----------------
// 256 threads, 64 nodes/tile. Each warp: 8 nodes (broadcast x), 4 rows/lane.
__global__ void __launch_bounds__(BT, 1)
k2(const int* __restrict__ nodes, const int* __restrict__ n2,
   const float* __restrict__ W2g, const float* __restrict__ wag,
   const float* __restrict__ bag, const float* __restrict__ wbg,
   const float* __restrict__ bbg, const float* __restrict__ wcg,
   const float* __restrict__ bcg, const int* __restrict__ psp,
   const int* __restrict__ nep, int Nq, int numTiles) {
    extern __shared__ float sh[];
    float* W2s = sh;                       // 128*128 swizzled
    float* was = W2s + 128 * 128;          // 128*128 swizzled
    float* wbs = was + 128 * 128;          // 64*128  swizzled
    float* xs  = wbs + 64 * 128;           // 64*128 node-major
    float* ys  = xs  + TILE * XP;          // 64*128 node-major
    float* waL = ys  + TILE * XP;          // 128 (last col of w_a)
    float* wcs = waL + 128;                // 64
    float* bas = wcs + 64;                 // 128
    float* bbs = bas + 128;                // 64

    int tid = threadIdx.x;
    for (int i = tid; i < 128 * 128; i += BT) {
        int r = i >> 7, k = i & 127;
        W2s[wswz(r, k)] = W2g[i];
    }
    for (int i = tid; i < 128 * 129; i += BT) {
        int r = i / 129, k = i - r * 129;
        if (k < 128) was[wswz(r, k)] = wag[i]; else waL[r] = wag[i];
    }
    for (int i = tid; i < 64 * 128; i += BT) {
        int r = i >> 7, k = i & 127;
        wbs[wswz(r, k)] = wbg[i];
    }
    if (tid < 64)  wcs[tid] = wcg[tid];
    if (tid < 128) bas[tid] = bag[tid];
    if (tid < 64)  bbs[tid] = bbg[tid];
    float rem = (float)(psp[0] - nep[0]);
    float bcv = bcg[0];
    __syncthreads();

    int lane = tid & 31;
    int wid  = tid >> 5;        // 0..7: node group of 8
    int jb   = wid << 3;        // first node of this warp's group
    int rx7  = lane & 7;

    for (int tile = blockIdx.x; tile < numTiles; tile += gridDim.x) {
        int base = tile * TILE;

        // ---- gather agg2: each warp its 8 nodes, lane covers 16B of 512B row
#pragma unroll
        for (int s = 0; s < 8; s++) {
            int nn = jb + s;
            int node = base + nn;
            float4 acc = make_float4(0.f, 0.f, 0.f, 0.f);
            if (node < Nq) {
                int q = nodes[node];
                acc = *(const float4*)(g_h1 + (size_t)q * HID + (lane << 2));
                const int* nb = n2 + (size_t)q * S2;
#pragma unroll
                for (int jj = 0; jj < S2; jj++) {
                    int qq = nb[jj];
                    float4 u = *(const float4*)(g_h1 + (size_t)qq * HID + (lane << 2));
                    acc.x += u.x; acc.y += u.y; acc.z += u.z; acc.w += u.w;
                }
                const float inv = 1.f / (float)(S2 + 1);
                acc.x *= inv; acc.y *= inv; acc.z *= inv; acc.w *= inv;
            }
            *(float4*)(xs + nn * XP + (lane << 2)) = acc;
        }
        __syncthreads();

        float v[4][8];

        // ---- GEMM1: emb = relu(W2 @ agg2), rows lane+32ro
        {
            const float init0[4] = {0.f, 0.f, 0.f, 0.f};
            gemmSw<4>(W2s + (lane << 7), xs + jb * XP, rx7, init0, v);
#pragma unroll
            for (int ro = 0; ro < 4; ro++)
#pragma unroll
                for (int j = 0; j < 8; j++)
                    ys[(jb + j) * XP + lane + (ro << 5)] = fmaxf(v[ro][j], 0.f);
        }
        __syncthreads();

        // ---- GEMM2: ya = relu(w_a @ [emb; rem] + b_a) -> xs
        {
            float init[4];
#pragma unroll
            for (int ro = 0; ro < 4; ro++) {
                int r = lane + (ro << 5);
                init[ro] = bas[r] + waL[r] * rem;
            }
            gemmSw<4>(was + (lane << 7), ys + jb * XP, rx7, init, v);
#pragma unroll
            for (int ro = 0; ro < 4; ro++)
#pragma unroll
                for (int j = 0; j < 8; j++)
                    xs[(jb + j) * XP + lane + (ro << 5)] = fmaxf(v[ro][j], 0.f);
        }
        __syncthreads();

        // ---- GEMM3 (rows lane, lane+32 of w_b) + wc dot, in-warp reduction
        {
            const float init0[2] = {0.f, 0.f};
            float v3[2][8];
            gemmSw<2>(wbs + (lane << 7), xs + jb * XP, rx7, init0, v3);
            float wc0 = wcs[lane],      bb0 = bbs[lane];
            float wc1 = wcs[lane + 32], bb1 = bbs[lane + 32];
            float c[8];
#pragma unroll
            for (int j = 0; j < 8; j++)
                c[j] = wc0 * fmaxf(v3[0][j] + bb0, 0.f)
                     + wc1 * fmaxf(v3[1][j] + bb1, 0.f);
#pragma unroll
            for (int off = 16; off; off >>= 1)
#pragma unroll
                for (int j = 0; j < 8; j++)
                    c[j] += __shfl_xor_sync(0xffffffffu, c[j], off);
            if (lane == 0) {
#pragma unroll
                for (int j = 0; j < 8; j++) {
                    int node = base + jb + j;
                    if (node < Nq) g_scores[node] = c[j] + bcv;
                }
            }
        }
        __syncthreads();   // protect xs before next tile's gather
    }
}

// ---------------- softmax (online max+sumexp) ----------------
__device__ __forceinline__ void sm_comb(float& m, float& s, float mo, float so) {
    if (mo > m) { float t = m; m = mo; mo = t; t = s; s = so; so = t; }
    if (so != 0.f) s += so * expf(mo - m);
}

__global__ void k_red1(int N) {
    float m = -FLT_MAX, s = 0.f;
    for (int i = blockIdx.x * blockDim.x + threadIdx.x; i < N; i += gridDim.x * blockDim.x) {
        float x = g_scores[i];
        if (x > m) { s = s * expf(m - x) + 1.f; m = x; }
        else        s += expf(x - m);
    }
#pragma unroll
    for (int off = 16; off; off >>= 1) {
        float mo = __shfl_xor_sync(0xffffffffu, m, off);
        float so = __shfl_xor_sync(0xffffffffu, s, off);
        sm_comb(m, s, mo, so);
    }
    __shared__ float shm[8], shs[8];
    int lane = threadIdx.x & 31, wid = threadIdx.x >> 5;
    if (lane == 0) { shm[wid] = m; shs[wid] = s; }
    __syncthreads();
    if (threadIdx.x < 32) {
        float m2 = (lane < 8) ? shm[lane] : -FLT_MAX;
        float s2 = (lane < 8) ? shs[lane] : 0.f;
#pragma unroll
        for (int off = 4; off; off >>= 1) {
            float mo = __shfl_xor_sync(0xffffffffu, m2, off);
            float so = __shfl_xor_sync(0xffffffffu, s2, off);
            sm_comb(m2, s2, mo, so);
        }
        if (threadIdx.x == 0) { g_pm[blockIdx.x] = m2; g_ps[blockIdx.x] = s2; }
    }
}

__global__ void k_red2(int RB) {
    int t = threadIdx.x;
    float m = (t < RB) ? g_pm[t] : -FLT_MAX;
    float s = (t < RB) ? g_ps[t] : 0.f;
#pragma unroll
    for (int off = 16; off; off >>= 1) {
        float mo = __shfl_xor_sync(0xffffffffu, m, off);
        float so = __shfl_xor_sync(0xffffffffu, s, off);
        sm_comb(m, s, mo, so);
    }
    __shared__ float shm[8], shs[8];
    int lane = t & 31, wid = t >> 5;
    if (lane == 0) { shm[wid] = m; shs[wid] = s; }
    __syncthreads();
    if (t < 32) {
        float m2 = (lane < 8) ? shm[lane] : -FLT_MAX;
        float s2 = (lane < 8) ? shs[lane] : 0.f;
#pragma unroll
        for (int off = 4; off; off >>= 1) {
            float mo = __shfl_xor_sync(0xffffffffu, m2, off);
            float so = __shfl_xor_sync(0xffffffffu, s2, off);
            sm_comb(m2, s2, mo, so);
        }
        if (t == 0) { g_MS[0] = m2; g_MS[1] = 1.f / s2; }
    }
}

__global__ void k_norm(float* __restrict__ out, int N) {
    int i = blockIdx.x * blockDim.x + threadIdx.x;
    if (i < N) out[i] = expf(g_scores[i] - g_MS[0]) * g_MS[1];
}

// ---------------- launch ----------------
static const int SMEM2 = (128 * 128 + 128 * 128 + 64 * 128 + TILE * XP + TILE * XP
                          + 128 + 64 + 128 + 64) * (int)sizeof(float);   // 230912 B

extern "C" void kernel_launch(void* const* d_in, const int* in_sizes, int n_in,
                              void* d_out, int out_size) {
    const int*   nodes = (const int*)d_in[0];
    const float* feat  = (const float*)d_in[1];
    const int*   n1    = (const int*)d_in[2];
    const int*   n2    = (const int*)d_in[3];
    const float* W1    = (const float*)d_in[4];
    const float* W2    = (const float*)d_in[5];
    const float* wa    = (const float*)d_in[6];
    const float* ba    = (const float*)d_in[7];
    const float* wb    = (const float*)d_in[8];
    const float* bb    = (const float*)d_in[9];
    const float* wc    = (const float*)d_in[10];
    const float* bc    = (const float*)d_in[11];
    const int*   ps    = (const int*)d_in[12];
    const int*   ne    = (const int*)d_in[13];

    int Nq = in_sizes[0];
    int NN = in_sizes[1] / 3;

    cudaFuncSetAttribute(k2, cudaFuncAttributeMaxDynamicSharedMemorySize, SMEM2);

    k_pad<<<(NN + 255) / 256, 256>>>(feat, NN);
    k_enc1<<<(NN + 7) / 8, 256>>>(n1, W1, NN);

    int numTiles = (Nq + TILE - 1) / TILE;
    k2<<<152, BT, SMEM2>>>(nodes, n2, W2, wa, ba, wb, bb, wc, bc, ps, ne, Nq, numTiles);

    k_red1<<<240, 256>>>(Nq);
    k_red2<<<1, 256>>>(240);
    k_norm<<<(Nq + 255) / 256, 256>>>((float*)d_out, Nq);
}

// round 12
// speedup vs baseline: 2.1854x; 1.0724x over previous
#include <cuda_runtime.h>
#include <cfloat>
#include <math.h>

#define NMAX   100000
#define HID    128
#define S1     50
#define S2     10
#define XP     128         // x-buffer stride (floats)
#define BT     256         // k2 threads (8 warps; each warp = independent pipeline)

// ---------------- scratch (static __device__, no allocations) ----------------
__device__ __align__(16) float4 g_featP[NMAX];                 // padded features
__device__ __align__(16) float  g_h1[(size_t)NMAX * HID];      // enc1 output
__device__ float g_scores[NMAX];
__device__ float g_pm[256];
__device__ float g_ps[256];
__device__ float g_MS[2];

typedef unsigned long long ull;

// ---------------- f32x2 helpers ----------------
__device__ __forceinline__ ull pack2f(float a, float b) {
    ull r;
    asm("mov.b64 %0, {%1, %2};" : "=l"(r) : "f"(a), "f"(b));
    return r;
}
__device__ __forceinline__ float2 unpack2f(ull v) {
    float2 r;
    asm("mov.b64 {%0, %1}, %2;" : "=f"(r.x), "=f"(r.y) : "l"(v));
    return r;
}
__device__ __forceinline__ void ffma2(ull& d, ull a, ull b) {
    asm("fma.rn.f32x2 %0, %1, %2, %0;" : "+l"(d) : "l"(a), "l"(b));
}

// swizzled weight index: element (r,k) lives at r*128 + ((k4 ^ (r&7))<<2) + (k&3)
__device__ __forceinline__ int wswz(int r, int k) {
    return (r << 7) + ((((k >> 2) ^ (r & 7)) << 2)) + (k & 3);
}

// GEMM slice: RPT rows (lane + 32*ro) x 8 nodes per warp, K=128.
// Wt = weight base + lane*128 (swizzled layout, row stride 32*128 per ro).
// xnb = xs + jb*XP: 8 node rows, k-contiguous; x loads are warp-broadcast.
template<int RPT>
__device__ __forceinline__ void gemmSw(const float* __restrict__ Wt,
                                       const float* __restrict__ xnb,
                                       int rx7, const float init[RPT],
                                       float v[RPT][8]) {
    ull acc[RPT][8];
#pragma unroll
    for (int ro = 0; ro < RPT; ro++) {
        ull ini = pack2f(init[ro], 0.f);
#pragma unroll
        for (int j = 0; j < 8; j++) acc[ro][j] = ini;
    }
#pragma unroll 2
    for (int k4 = 0; k4 < 32; k4++) {
        int soff = ((k4 ^ rx7) << 2);
        ulonglong2 w[RPT];
#pragma unroll
        for (int ro = 0; ro < RPT; ro++)
            w[ro] = *(const ulonglong2*)(Wt + (ro << 12) + soff);   // ro*32*128
#pragma unroll
        for (int j = 0; j < 8; j++) {
            ulonglong2 xp = *(const ulonglong2*)(xnb + j * XP + (k4 << 2));
#pragma unroll
            for (int ro = 0; ro < RPT; ro++) {
                ffma2(acc[ro][j], xp.x, w[ro].x);
                ffma2(acc[ro][j], xp.y, w[ro].y);
            }
        }
    }
#pragma unroll
    for (int ro = 0; ro < RPT; ro++)
#pragma unroll
        for (int j = 0; j < 8; j++) {
            float2 p = unpack2f(acc[ro][j]);
            v[ro][j] = p.x + p.y;
        }
}

// ---------------- kernel 0: pad features [N,3] -> float4 ----------------
__global__ void k_pad(const float* __restrict__ f, int NN) {
    int i = blockIdx.x * blockDim.x + threadIdx.x;
    if (i < NN) {
        g_featP[i] = make_float4(f[3 * i], f[3 * i + 1], f[3 * i + 2], 0.f);
    }
}

// ---------------- kernel 1: enc1 -> h1, one warp per node ----------------
__global__ void k_enc1(const int* __restrict__ n1, const float* __restrict__ W1, int NN) {
    int node = (blockIdx.x << 3) + (threadIdx.x >> 5);
    int lane = threadIdx.x & 31;
    if (node >= NN) return;
    const int* nb = n1 + (size_t)node * S1;
    float a0, a1, a2;
    {
        int i1 = nb[lane];
        float4 f = g_featP[i1];
        a0 = f.x; a1 = f.y; a2 = f.z;
    }
    if (lane < S1 - 32) {
        int i2 = nb[lane + 32];
        float4 f = g_featP[i2];
        a0 += f.x; a1 += f.y; a2 += f.z;
    }
#pragma unroll
    for (int off = 16; off; off >>= 1) {
        a0 += __shfl_xor_sync(0xffffffffu, a0, off);
        a1 += __shfl_xor_sync(0xffffffffu, a1, off);
        a2 += __shfl_xor_sync(0xffffffffu, a2, off);
    }
    float4 fs = g_featP[node];
    const float inv = 1.f / (float)(S1 + 1);
    a0 = (a0 + fs.x) * inv;
    a1 = (a1 + fs.y) * inv;
    a2 = (a2 + fs.z) * inv;
    const float* w = W1 + lane * 12;     // rows 4*lane .. 4*lane+3
    float4 h;
    h.x = fmaxf(fmaf(a0, w[0], fmaf(a1, w[1],  a2 * w[2])),  0.f);
    h.y = fmaxf(fmaf(a0, w[3], fmaf(a1, w[4],  a2 * w[5])),  0.f);
    h.z = fmaxf(fmaf(a0, w[6], fmaf(a1, w[7],  a2 * w[8])),  0.f);
    h.w = fmaxf(fmaf(a0, w[9], fmaf(a1, w[10], a2 * w[11])), 0.f);
    *(float4*)(g_h1 + (size_t)node * HID + (lane << 2)) = h;
}

// ---------------- kernel 2: enc2 + MLP + scores ----------------
// 256 threads. Each warp = independent pipeline over 8-node groups:
// gather -> GEMM1 -> GEMM2 -> GEMM3+dot, only __syncwarp between phases.
__global__ void __launch_bounds__(BT, 1)
k2(const int* __restrict__ nodes, const int* __restrict__ n2,
   const float* __restrict__ W2g, const float* __restrict__ wag,
   const float* __restrict__ bag, const float* __restrict__ wbg,
   const float* __restrict__ bbg, const float* __restrict__ wcg,
   const float* __restrict__ bcg, const int* __restrict__ psp,
   const int* __restrict__ nep, int Nq, int numGroups) {
    extern __shared__ float sh[];
    float* W2s = sh;                       // 128*128 swizzled
    float* was = W2s + 128 * 128;          // 128*128 swizzled
    float* wbs = was + 128 * 128;          // 64*128  swizzled
    float* xs  = wbs + 64 * 128;           // 64*128 node-major (8 rows per warp)
    float* ys  = xs  + 64 * XP;            // 64*128 node-major
    float* waL = ys  + 64 * XP;            // 128 (last col of w_a)
    float* wcs = waL + 128;                // 64
    float* bas = wcs + 64;                 // 128
    float* bbs = bas + 128;                // 64

    int tid = threadIdx.x;
    for (int i = tid; i < 128 * 128; i += BT) {
        int r = i >> 7, k = i & 127;
        W2s[wswz(r, k)] = W2g[i];
    }
    for (int i = tid; i < 128 * 129; i += BT) {
        int r = i / 129, k = i - r * 129;
        if (k < 128) was[wswz(r, k)] = wag[i]; else waL[r] = wag[i];
    }
    for (int i = tid; i < 64 * 128; i += BT) {
        int r = i >> 7, k = i & 127;
        wbs[wswz(r, k)] = wbg[i];
    }
    if (tid < 64)  wcs[tid] = wcg[tid];
    if (tid < 128) bas[tid] = bag[tid];
    if (tid < 64)  bbs[tid] = bbg[tid];
    float rem = (float)(psp[0] - nep[0]);
    float bcv = bcg[0];
    __syncthreads();   // weights ready; afterwards warps never interact

    int lane = tid & 31;
    int wid  = tid >> 5;        // 0..7
    int jb   = wid << 3;        // this warp's 8 smem rows
    int rx7  = lane & 7;

    for (int grp = (blockIdx.x << 3) + wid; grp < numGroups; grp += (gridDim.x << 3)) {
        int base = grp << 3;

        // ---- gather agg2: 8 nodes, lane covers 16B of each 512B h1 row
#pragma unroll
        for (int s = 0; s < 8; s++) {
            int node = base + s;
            float4 acc = make_float4(0.f, 0.f, 0.f, 0.f);
            if (node < Nq) {
                int q = nodes[node];
                acc = *(const float4*)(g_h1 + (size_t)q * HID + (lane << 2));
                const int* nb = n2 + (size_t)q * S2;
#pragma unroll
                for (int jj = 0; jj < S2; jj++) {
                    int qq = nb[jj];
                    float4 u = *(const float4*)(g_h1 + (size_t)qq * HID + (lane << 2));
                    acc.x += u.x; acc.y += u.y; acc.z += u.z; acc.w += u.w;
                }
                const float inv = 1.f / (float)(S2 + 1);
                acc.x *= inv; acc.y *= inv; acc.z *= inv; acc.w *= inv;
            }
            *(float4*)(xs + (jb + s) * XP + (lane << 2)) = acc;
        }
        __syncwarp();

        float v[4][8];

        // ---- GEMM1: emb = relu(W2 @ agg2), rows lane+32ro
        {
            const float init0[4] = {0.f, 0.f, 0.f, 0.f};
            gemmSw<4>(W2s + (lane << 7), xs + jb * XP, rx7, init0, v);
#pragma unroll
            for (int ro = 0; ro < 4; ro++)
#pragma unroll
                for (int j = 0; j < 8; j++)
                    ys[(jb + j) * XP + lane + (ro << 5)] = fmaxf(v[ro][j], 0.f);
        }
        __syncwarp();

        // ---- GEMM2: ya = relu(w_a @ [emb; rem] + b_a) -> xs
        {
            float init[4];
#pragma unroll
            for (int ro = 0; ro < 4; ro++) {
                int r = lane + (ro << 5);
                init[ro] = bas[r] + waL[r] * rem;
            }
            gemmSw<4>(was + (lane << 7), ys + jb * XP, rx7, init, v);
#pragma unroll
            for (int ro = 0; ro < 4; ro++)
#pragma unroll
                for (int j = 0; j < 8; j++)
                    xs[(jb + j) * XP + lane + (ro << 5)] = fmaxf(v[ro][j], 0.f);
        }
        __syncwarp();

        // ---- GEMM3 (rows lane, lane+32 of w_b) + wc dot, in-warp reduction
        {
            const float init0[2] = {0.f, 0.f};
            float v3[2][8];
            gemmSw<2>(wbs + (lane << 7), xs + jb * XP, rx7, init0, v3);
            float wc0 = wcs[lane],      bb0 = bbs[lane];
            float wc1 = wcs[lane + 32], bb1 = bbs[lane + 32];
            float c[8];
#pragma unroll
            for (int j = 0; j < 8; j++)
                c[j] = wc0 * fmaxf(v3[0][j] + bb0, 0.f)
                     + wc1 * fmaxf(v3[1][j] + bb1, 0.f);
#pragma unroll
            for (int off = 16; off; off >>= 1)
#pragma unroll
                for (int j = 0; j < 8; j++)
                    c[j] += __shfl_xor_sync(0xffffffffu, c[j], off);
            if (lane == 0) {
#pragma unroll
                for (int j = 0; j < 8; j++) {
                    int node = base + j;
                    if (node < Nq) g_scores[node] = c[j] + bcv;
                }
            }
        }
        __syncwarp();   // xs safe to overwrite in next iteration's gather
    }
}

// ---------------- softmax (online max+sumexp) ----------------
__device__ __forceinline__ void sm_comb(float& m, float& s, float mo, float so) {
    if (mo > m) { float t = m; m = mo; mo = t; t = s; s = so; so = t; }
    if (so != 0.f) s += so * expf(mo - m);
}

__global__ void k_red1(int N) {
    float m = -FLT_MAX, s = 0.f;
    for (int i = blockIdx.x * blockDim.x + threadIdx.x; i < N; i += gridDim.x * blockDim.x) {
        float x = g_scores[i];
        if (x > m) { s = s * expf(m - x) + 1.f; m = x; }
        else        s += expf(x - m);
    }
#pragma unroll
    for (int off = 16; off; off >>= 1) {
        float mo = __shfl_xor_sync(0xffffffffu, m, off);
        float so = __shfl_xor_sync(0xffffffffu, s, off);
        sm_comb(m, s, mo, so);
    }
    __shared__ float shm[8], shs[8];
    int lane = threadIdx.x & 31, wid = threadIdx.x >> 5;
    if (lane == 0) { shm[wid] = m; shs[wid] = s; }
    __syncthreads();
    if (threadIdx.x < 32) {
        float m2 = (lane < 8) ? shm[lane] : -FLT_MAX;
        float s2 = (lane < 8) ? shs[lane] : 0.f;
#pragma unroll
        for (int off = 4; off; off >>= 1) {
            float mo = __shfl_xor_sync(0xffffffffu, m2, off);
            float so = __shfl_xor_sync(0xffffffffu, s2, off);
            sm_comb(m2, s2, mo, so);
        }
        if (threadIdx.x == 0) { g_pm[blockIdx.x] = m2; g_ps[blockIdx.x] = s2; }
    }
}

__global__ void k_red2(int RB) {
    int t = threadIdx.x;
    float m = (t < RB) ? g_pm[t] : -FLT_MAX;
    float s = (t < RB) ? g_ps[t] : 0.f;
#pragma unroll
    for (int off = 16; off; off >>= 1) {
        float mo = __shfl_xor_sync(0xffffffffu, m, off);
        float so = __shfl_xor_sync(0xffffffffu, s, off);
        sm_comb(m, s, mo, so);
    }
    __shared__ float shm[8], shs[8];
    int lane = t & 31, wid = t >> 5;
    if (lane == 0) { shm[wid] = m; shs[wid] = s; }
    __syncthreads();
    if (t < 32) {
        float m2 = (lane < 8) ? shm[lane] : -FLT_MAX;
        float s2 = (lane < 8) ? shs[lane] : 0.f;
#pragma unroll
        for (int off = 4; off; off >>= 1) {
            float mo = __shfl_xor_sync(0xffffffffu, m2, off);
            float so = __shfl_xor_sync(0xffffffffu, s2, off);
            sm_comb(m2, s2, mo, so);
        }
        if (t == 0) { g_MS[0] = m2; g_MS[1] = 1.f / s2; }
    }
}

__global__ void k_norm(float* __restrict__ out, int N) {
    int i = blockIdx.x * blockDim.x + threadIdx.x;
    if (i < N) out[i] = expf(g_scores[i] - g_MS[0]) * g_MS[1];
}

// ---------------- launch ----------------
static const int SMEM2 = (128 * 128 + 128 * 128 + 64 * 128 + 64 * XP + 64 * XP
                          + 128 + 64 + 128 + 64) * (int)sizeof(float);   // 230912 B

extern "C" void kernel_launch(void* const* d_in, const int* in_sizes, int n_in,
                              void* d_out, int out_size) {
    const int*   nodes = (const int*)d_in[0];
    const float* feat  = (const float*)d_in[1];
    const int*   n1    = (const int*)d_in[2];
    const int*   n2    = (const int*)d_in[3];
    const float* W1    = (const float*)d_in[4];
    const float* W2    = (const float*)d_in[5];
    const float* wa    = (const float*)d_in[6];
    const float* ba    = (const float*)d_in[7];
    const float* wb    = (const float*)d_in[8];
    const float* bb    = (const float*)d_in[9];
    const float* wc    = (const float*)d_in[10];
    const float* bc    = (const float*)d_in[11];
    const int*   ps    = (const int*)d_in[12];
    const int*   ne    = (const int*)d_in[13];

    int Nq = in_sizes[0];
    int NN = in_sizes[1] / 3;

    cudaFuncSetAttribute(k2, cudaFuncAttributeMaxDynamicSharedMemorySize, SMEM2);

    k_pad<<<(NN + 255) / 256, 256>>>(feat, NN);
    k_enc1<<<(NN + 7) / 8, 256>>>(n1, W1, NN);

    int numGroups = (Nq + 7) / 8;
    k2<<<152, BT, SMEM2>>>(nodes, n2, W2, wa, ba, wb, bb, wc, bc, ps, ne, Nq, numGroups);

    k_red1<<<240, 256>>>(Nq);
    k_red2<<<1, 256>>>(240);
    k_norm<<<(Nq + 255) / 256, 256>>>((float*)d_out, Nq);
}

// round 13
// speedup vs baseline: 2.2648x; 1.0363x over previous
#include <cuda_runtime.h>
#include <cfloat>
#include <math.h>

#define NMAX   100000
#define HID    128
#define S1     50
#define S2     10
#define XP     128         // x-buffer stride (floats)
#define BT     512         // k2 threads (16 warps; each warp = independent pipeline)

// ---------------- scratch (static __device__, no allocations) ----------------
__device__ __align__(16) float4 g_featP[NMAX];                 // padded features
__device__ __align__(16) float  g_h1[(size_t)NMAX * HID];      // enc1 output
__device__ float g_scores[NMAX];
__device__ float g_pm[256];
__device__ float g_ps[256];
__device__ float g_MS[2];

typedef unsigned long long ull;

// ---------------- f32x2 helpers ----------------
__device__ __forceinline__ ull pack2f(float a, float b) {
    ull r;
    asm("mov.b64 %0, {%1, %2};" : "=l"(r) : "f"(a), "f"(b));
    return r;
}
__device__ __forceinline__ float2 unpack2f(ull v) {
    float2 r;
    asm("mov.b64 {%0, %1}, %2;" : "=f"(r.x), "=f"(r.y) : "l"(v));
    return r;
}
__device__ __forceinline__ void ffma2(ull& d, ull a, ull b) {
    asm("fma.rn.f32x2 %0, %1, %2, %0;" : "+l"(d) : "l"(a), "l"(b));
}

// swizzled weight index: element (r,k) lives at r*128 + ((k4 ^ (r&7))<<2) + (k&3)
__device__ __forceinline__ int wswz(int r, int k) {
    return (r << 7) + ((((k >> 2) ^ (r & 7)) << 2)) + (k & 3);
}

// GEMM slice: RPT rows (lane + 32*ro) x NJ nodes per warp, K=128.
// Wt = weight base + lane*128 (swizzled layout, row stride 32*128 per ro).
// xnb: NJ node rows, k-contiguous; x loads are warp-broadcast.
template<int RPT, int NJ>
__device__ __forceinline__ void gemmSw(const float* __restrict__ Wt,
                                       const float* __restrict__ xnb,
                                       int rx7, const float init[RPT],
                                       float v[RPT][NJ]) {
    ull acc[RPT][NJ];
#pragma unroll
    for (int ro = 0; ro < RPT; ro++) {
        ull ini = pack2f(init[ro], 0.f);
#pragma unroll
        for (int j = 0; j < NJ; j++) acc[ro][j] = ini;
    }
#pragma unroll 2
    for (int k4 = 0; k4 < 32; k4++) {
        int soff = ((k4 ^ rx7) << 2);
        ulonglong2 w[RPT];
#pragma unroll
        for (int ro = 0; ro < RPT; ro++)
            w[ro] = *(const ulonglong2*)(Wt + (ro << 12) + soff);   // ro*32*128
#pragma unroll
        for (int j = 0; j < NJ; j++) {
            ulonglong2 xp = *(const ulonglong2*)(xnb + j * XP + (k4 << 2));
#pragma unroll
            for (int ro = 0; ro < RPT; ro++) {
                ffma2(acc[ro][j], xp.x, w[ro].x);
                ffma2(acc[ro][j], xp.y, w[ro].y);
            }
        }
    }
#pragma unroll
    for (int ro = 0; ro < RPT; ro++)
#pragma unroll
        for (int j = 0; j < NJ; j++) {
            float2 p = unpack2f(acc[ro][j]);
            v[ro][j] = p.x + p.y;
        }
}

// ---------------- kernel 0: pad features [N,3] -> float4 ----------------
__global__ void k_pad(const float* __restrict__ f, int NN) {
    int i = blockIdx.x * blockDim.x + threadIdx.x;
    if (i < NN) {
        g_featP[i] = make_float4(f[3 * i], f[3 * i + 1], f[3 * i + 2], 0.f);
    }
}

// ---------------- kernel 1: enc1 -> h1, one warp per node ----------------
__global__ void k_enc1(const int* __restrict__ n1, const float* __restrict__ W1, int NN) {
    int node = (blockIdx.x << 3) + (threadIdx.x >> 5);
    int lane = threadIdx.x & 31;
    if (node >= NN) return;
    const int* nb = n1 + (size_t)node * S1;
    float a0, a1, a2;
    {
        int i1 = nb[lane];
        float4 f = g_featP[i1];
        a0 = f.x; a1 = f.y; a2 = f.z;
    }
    if (lane < S1 - 32) {
        int i2 = nb[lane + 32];
        float4 f = g_featP[i2];
        a0 += f.x; a1 += f.y; a2 += f.z;
    }
#pragma unroll
    for (int off = 16; off; off >>= 1) {
        a0 += __shfl_xor_sync(0xffffffffu, a0, off);
        a1 += __shfl_xor_sync(0xffffffffu, a1, off);
        a2 += __shfl_xor_sync(0xffffffffu, a2, off);
    }
    float4 fs = g_featP[node];
    const float inv = 1.f / (float)(S1 + 1);
    a0 = (a0 + fs.x) * inv;
    a1 = (a1 + fs.y) * inv;
    a2 = (a2 + fs.z) * inv;
    const float* w = W1 + lane * 12;     // rows 4*lane .. 4*lane+3
    float4 h;
    h.x = fmaxf(fmaf(a0, w[0], fmaf(a1, w[1],  a2 * w[2])),  0.f);
    h.y = fmaxf(fmaf(a0, w[3], fmaf(a1, w[4],  a2 * w[5])),  0.f);
    h.z = fmaxf(fmaf(a0, w[6], fmaf(a1, w[7],  a2 * w[8])),  0.f);
    h.w = fmaxf(fmaf(a0, w[9], fmaf(a1, w[10], a2 * w[11])), 0.f);
    *(float4*)(g_h1 + (size_t)node * HID + (lane << 2)) = h;
}

// ---------------- kernel 2: enc2 + MLP + scores ----------------
// 512 threads, 16 warps. Each warp = independent pipeline over 4-node groups:
// gather -> GEMM1 -> GEMM2 -> GEMM3+dot, only __syncwarp between phases.
__global__ void __launch_bounds__(BT, 1)
k2(const int* __restrict__ nodes, const int* __restrict__ n2,
   const float* __restrict__ W2g, const float* __restrict__ wag,
   const float* __restrict__ bag, const float* __restrict__ wbg,
   const float* __restrict__ bbg, const float* __restrict__ wcg,
   const float* __restrict__ bcg, const int* __restrict__ psp,
   const int* __restrict__ nep, int Nq, int numGroups) {
    extern __shared__ float sh[];
    float* W2s = sh;                       // 128*128 swizzled
    float* was = W2s + 128 * 128;          // 128*128 swizzled
    float* wbs = was + 128 * 128;          // 64*128  swizzled
    float* xs  = wbs + 64 * 128;           // 64*128 node-major (4 rows per warp)
    float* ys  = xs  + 64 * XP;            // 64*128 node-major
    float* waL = ys  + 64 * XP;            // 128 (last col of w_a)
    float* wcs = waL + 128;                // 64
    float* bas = wcs + 64;                 // 128
    float* bbs = bas + 128;                // 64

    int tid = threadIdx.x;
    for (int i = tid; i < 128 * 128; i += BT) {
        int r = i >> 7, k = i & 127;
        W2s[wswz(r, k)] = W2g[i];
    }
    for (int i = tid; i < 128 * 129; i += BT) {
        int r = i / 129, k = i - r * 129;
        if (k < 128) was[wswz(r, k)] = wag[i]; else waL[r] = wag[i];
    }
    for (int i = tid; i < 64 * 128; i += BT) {
        int r = i >> 7, k = i & 127;
        wbs[wswz(r, k)] = wbg[i];
    }
    if (tid < 64)  wcs[tid] = wcg[tid];
    if (tid < 128) bas[tid] = bag[tid];
    if (tid < 64)  bbs[tid] = bbg[tid];
    float rem = (float)(psp[0] - nep[0]);
    float bcv = bcg[0];
    __syncthreads();   // weights ready; afterwards warps never interact

    int lane = tid & 31;
    int wid  = tid >> 5;        // 0..15
    int jb   = wid << 2;        // this warp's 4 smem rows
    int rx7  = lane & 7;

    for (int grp = (blockIdx.x << 4) + wid; grp < numGroups; grp += (gridDim.x << 4)) {
        int base = grp << 2;

        // ---- gather agg2: 4 nodes, lane covers 16B of each 512B h1 row
#pragma unroll
        for (int s = 0; s < 4; s++) {
            int node = base + s;
            float4 acc = make_float4(0.f, 0.f, 0.f, 0.f);
            if (node < Nq) {
                int q = nodes[node];
                acc = *(const float4*)(g_h1 + (size_t)q * HID + (lane << 2));
                const int* nb = n2 + (size_t)q * S2;
#pragma unroll
                for (int jj = 0; jj < S2; jj++) {
                    int qq = nb[jj];
                    float4 u = *(const float4*)(g_h1 + (size_t)qq * HID + (lane << 2));
                    acc.x += u.x; acc.y += u.y; acc.z += u.z; acc.w += u.w;
                }
                const float inv = 1.f / (float)(S2 + 1);
                acc.x *= inv; acc.y *= inv; acc.z *= inv; acc.w *= inv;
            }
            *(float4*)(xs + (jb + s) * XP + (lane << 2)) = acc;
        }
        __syncwarp();

        float v[4][4];

        // ---- GEMM1: emb = relu(W2 @ agg2), rows lane+32ro
        {
            const float init0[4] = {0.f, 0.f, 0.f, 0.f};
            gemmSw<4, 4>(W2s + (lane << 7), xs + jb * XP, rx7, init0, v);
#pragma unroll
            for (int ro = 0; ro < 4; ro++)
#pragma unroll
                for (int j = 0; j < 4; j++)
                    ys[(jb + j) * XP + lane + (ro << 5)] = fmaxf(v[ro][j], 0.f);
        }
        __syncwarp();

        // ---- GEMM2: ya = relu(w_a @ [emb; rem] + b_a) -> xs
        {
            float init[4];
#pragma unroll
            for (int ro = 0; ro < 4; ro++) {
                int r = lane + (ro << 5);
                init[ro] = bas[r] + waL[r] * rem;
            }
            gemmSw<4, 4>(was + (lane << 7), ys + jb * XP, rx7, init, v);
#pragma unroll
            for (int ro = 0; ro < 4; ro++)
#pragma unroll
                for (int j = 0; j < 4; j++)
                    xs[(jb + j) * XP + lane + (ro << 5)] = fmaxf(v[ro][j], 0.f);
        }
        __syncwarp();

        // ---- GEMM3 (rows lane, lane+32 of w_b) + wc dot, in-warp reduction
        {
            const float init0[2] = {0.f, 0.f};
            float v3[2][4];
            gemmSw<2, 4>(wbs + (lane << 7), xs + jb * XP, rx7, init0, v3);
            float wc0 = wcs[lane],      bb0 = bbs[lane];
            float wc1 = wcs[lane + 32], bb1 = bbs[lane + 32];
            float c[4];
#pragma unroll
            for (int j = 0; j < 4; j++)
                c[j] = wc0 * fmaxf(v3[0][j] + bb0, 0.f)
                     + wc1 * fmaxf(v3[1][j] + bb1, 0.f);
#pragma unroll
            for (int off = 16; off; off >>= 1)
#pragma unroll
                for (int j = 0; j < 4; j++)
                    c[j] += __shfl_xor_sync(0xffffffffu, c[j], off);
            if (lane == 0) {
#pragma unroll
                for (int j = 0; j < 4; j++) {
                    int node = base + j;
                    if (node < Nq) g_scores[node] = c[j] + bcv;
                }
            }
        }
        __syncwarp();   // xs safe to overwrite in next iteration's gather
    }
}

// ---------------- softmax (online max+sumexp) ----------------
__device__ __forceinline__ void sm_comb(float& m, float& s, float mo, float so) {
    if (mo > m) { float t = m; m = mo; mo = t; t = s; s = so; so = t; }
    if (so != 0.f) s += so * expf(mo - m);
}

__global__ void k_red1(int N) {
    float m = -FLT_MAX, s = 0.f;
    for (int i = blockIdx.x * blockDim.x + threadIdx.x; i < N; i += gridDim.x * blockDim.x) {
        float x = g_scores[i];
        if (x > m) { s = s * expf(m - x) + 1.f; m = x; }
        else        s += expf(x - m);
    }
#pragma unroll
    for (int off = 16; off; off >>= 1) {
        float mo = __shfl_xor_sync(0xffffffffu, m, off);
        float so = __shfl_xor_sync(0xffffffffu, s, off);
        sm_comb(m, s, mo, so);
    }
    __shared__ float shm[8], shs[8];
    int lane = threadIdx.x & 31, wid = threadIdx.x >> 5;
    if (lane == 0) { shm[wid] = m; shs[wid] = s; }
    __syncthreads();
    if (threadIdx.x < 32) {
        float m2 = (lane < 8) ? shm[lane] : -FLT_MAX;
        float s2 = (lane < 8) ? shs[lane] : 0.f;
#pragma unroll
        for (int off = 4; off; off >>= 1) {
            float mo = __shfl_xor_sync(0xffffffffu, m2, off);
            float so = __shfl_xor_sync(0xffffffffu, s2, off);
            sm_comb(m2, s2, mo, so);
        }
        if (threadIdx.x == 0) { g_pm[blockIdx.x] = m2; g_ps[blockIdx.x] = s2; }
    }
}

__global__ void k_red2(int RB) {
    int t = threadIdx.x;
    float m = (t < RB) ? g_pm[t] : -FLT_MAX;
    float s = (t < RB) ? g_ps[t] : 0.f;
#pragma unroll
    for (int off = 16; off; off >>= 1) {
        float mo = __shfl_xor_sync(0xffffffffu, m, off);
        float so = __shfl_xor_sync(0xffffffffu, s, off);
        sm_comb(m, s, mo, so);
    }
    __shared__ float shm[8], shs[8];
    int lane = t & 31, wid = t >> 5;
    if (lane == 0) { shm[wid] = m; shs[wid] = s; }
    __syncthreads();
    if (t < 32) {
        float m2 = (lane < 8) ? shm[lane] : -FLT_MAX;
        float s2 = (lane < 8) ? shs[lane] : 0.f;
#pragma unroll
        for (int off = 4; off; off >>= 1) {
            float mo = __shfl_xor_sync(0xffffffffu, m2, off);
            float so = __shfl_xor_sync(0xffffffffu, s2, off);
            sm_comb(m2, s2, mo, so);
        }
        if (t == 0) { g_MS[0] = m2; g_MS[1] = 1.f / s2; }
    }
}

__global__ void k_norm(float* __restrict__ out, int N) {
    int i = blockIdx.x * blockDim.x + threadIdx.x;
    if (i < N) out[i] = expf(g_scores[i] - g_MS[0]) * g_MS[1];
}

// ---------------- launch ----------------
static const int SMEM2 = (128 * 128 + 128 * 128 + 64 * 128 + 64 * XP + 64 * XP
                          + 128 + 64 + 128 + 64) * (int)sizeof(float);   // 230912 B

extern "C" void kernel_launch(void* const* d_in, const int* in_sizes, int n_in,
                              void* d_out, int out_size) {
    const int*   nodes = (const int*)d_in[0];
    const float* feat  = (const float*)d_in[1];
    const int*   n1    = (const int*)d_in[2];
    const int*   n2    = (const int*)d_in[3];
    const float* W1    = (const float*)d_in[4];
    const float* W2    = (const float*)d_in[5];
    const float* wa    = (const float*)d_in[6];
    const float* ba    = (const float*)d_in[7];
    const float* wb    = (const float*)d_in[8];
    const float* bb    = (const float*)d_in[9];
    const float* wc    = (const float*)d_in[10];
    const float* bc    = (const float*)d_in[11];
    const int*   ps    = (const int*)d_in[12];
    const int*   ne    = (const int*)d_in[13];

    int Nq = in_sizes[0];
    int NN = in_sizes[1] / 3;

    cudaFuncSetAttribute(k2, cudaFuncAttributeMaxDynamicSharedMemorySize, SMEM2);

    k_pad<<<(NN + 255) / 256, 256>>>(feat, NN);
    k_enc1<<<(NN + 7) / 8, 256>>>(n1, W1, NN);

    int numGroups = (Nq + 3) / 4;
    k2<<<152, BT, SMEM2>>>(nodes, n2, W2, wa, ba, wb, bb, wc, bc, ps, ne, Nq, numGroups);

    k_red1<<<240, 256>>>(Nq);
    k_red2<<<1, 256>>>(240);
    k_norm<<<(Nq + 255) / 256, 256>>>((float*)d_out, Nq);
}

// round 14
// speedup vs baseline: 2.2786x; 1.0061x over previous
#include <cuda_runtime.h>
#include <cfloat>
#include <math.h>

#define NMAX   100000
#define HID    128
#define S1     50
#define S2     10
#define XP     128         // x-buffer stride (floats)
#define BT     384         // 12 warps; each warp = independent pipeline
#define NWARP  12

// ---------------- scratch (static __device__, no allocations) ----------------
__device__ __align__(16) float4 g_featP[NMAX];                 // padded features
__device__ __align__(16) float  g_h1[(size_t)NMAX * HID];      // enc1 output
__device__ __align__(16) float  g_emb[(size_t)NMAX * HID];     // GEMM1 output
__device__ float g_scores[NMAX];
__device__ float g_pm[256];
__device__ float g_ps[256];
__device__ float g_MS[2];

typedef unsigned long long ull;

// ---------------- f32x2 helpers ----------------
__device__ __forceinline__ ull pack2f(float a, float b) {
    ull r;
    asm("mov.b64 %0, {%1, %2};" : "=l"(r) : "f"(a), "f"(b));
    return r;
}
__device__ __forceinline__ float2 unpack2f(ull v) {
    float2 r;
    asm("mov.b64 {%0, %1}, %2;" : "=f"(r.x), "=f"(r.y) : "l"(v));
    return r;
}
__device__ __forceinline__ void ffma2(ull& d, ull a, ull b) {
    asm("fma.rn.f32x2 %0, %1, %2, %0;" : "+l"(d) : "l"(a), "l"(b));
}

// swizzled weight index: element (r,k) lives at r*128 + ((k4 ^ (r&7))<<2) + (k&3)
__device__ __forceinline__ int wswz(int r, int k) {
    return (r << 7) + ((((k >> 2) ^ (r & 7)) << 2)) + (k & 3);
}

// GEMM slice: RPT rows (lane + 32*ro) x 8 nodes per warp, K=128.
// Wt = weight base + lane*128 (swizzled, row stride 32*128 per ro).
// xnb: 8 node rows, k-contiguous; x loads are warp-broadcast.
template<int RPT>
__device__ __forceinline__ void gemmSw(const float* __restrict__ Wt,
                                       const float* __restrict__ xnb,
                                       int rx7, const float init[RPT],
                                       float v[RPT][8]) {
    ull acc[RPT][8];
#pragma unroll
    for (int ro = 0; ro < RPT; ro++) {
        ull ini = pack2f(init[ro], 0.f);
#pragma unroll
        for (int j = 0; j < 8; j++) acc[ro][j] = ini;
    }
#pragma unroll 2
    for (int k4 = 0; k4 < 32; k4++) {
        int soff = ((k4 ^ rx7) << 2);
        ulonglong2 w[RPT];
#pragma unroll
        for (int ro = 0; ro < RPT; ro++)
            w[ro] = *(const ulonglong2*)(Wt + (ro << 12) + soff);   // ro*32*128
#pragma unroll
        for (int j = 0; j < 8; j++) {
            ulonglong2 xp = *(const ulonglong2*)(xnb + j * XP + (k4 << 2));
#pragma unroll
            for (int ro = 0; ro < RPT; ro++) {
                ffma2(acc[ro][j], xp.x, w[ro].x);
                ffma2(acc[ro][j], xp.y, w[ro].y);
            }
        }
    }
#pragma unroll
    for (int ro = 0; ro < RPT; ro++)
#pragma unroll
        for (int j = 0; j < 8; j++) {
            float2 p = unpack2f(acc[ro][j]);
            v[ro][j] = p.x + p.y;
        }
}

// ---------------- kernel 0: pad features [N,3] -> float4 ----------------
__global__ void k_pad(const float* __restrict__ f, int NN) {
    int i = blockIdx.x * blockDim.x + threadIdx.x;
    if (i < NN) {
        g_featP[i] = make_float4(f[3 * i], f[3 * i + 1], f[3 * i + 2], 0.f);
    }
}

// ---------------- kernel 1: enc1 -> h1, one warp per node ----------------
__global__ void k_enc1(const int* __restrict__ n1, const float* __restrict__ W1, int NN) {
    int node = (blockIdx.x << 3) + (threadIdx.x >> 5);
    int lane = threadIdx.x & 31;
    if (node >= NN) return;
    const int* nb = n1 + (size_t)node * S1;
    float a0, a1, a2;
    {
        int i1 = nb[lane];
        float4 f = g_featP[i1];
        a0 = f.x; a1 = f.y; a2 = f.z;
    }
    if (lane < S1 - 32) {
        int i2 = nb[lane + 32];
        float4 f = g_featP[i2];
        a0 += f.x; a1 += f.y; a2 += f.z;
    }
#pragma unroll
    for (int off = 16; off; off >>= 1) {
        a0 += __shfl_xor_sync(0xffffffffu, a0, off);
        a1 += __shfl_xor_sync(0xffffffffu, a1, off);
        a2 += __shfl_xor_sync(0xffffffffu, a2, off);
    }
    float4 fs = g_featP[node];
    const float inv = 1.f / (float)(S1 + 1);
    a0 = (a0 + fs.x) * inv;
    a1 = (a1 + fs.y) * inv;
    a2 = (a2 + fs.z) * inv;
    const float* w = W1 + lane * 12;     // rows 4*lane .. 4*lane+3
    float4 h;
    h.x = fmaxf(fmaf(a0, w[0], fmaf(a1, w[1],  a2 * w[2])),  0.f);
    h.y = fmaxf(fmaf(a0, w[3], fmaf(a1, w[4],  a2 * w[5])),  0.f);
    h.z = fmaxf(fmaf(a0, w[6], fmaf(a1, w[7],  a2 * w[8])),  0.f);
    h.w = fmaxf(fmaf(a0, w[9], fmaf(a1, w[10], a2 * w[11])), 0.f);
    *(float4*)(g_h1 + (size_t)node * HID + (lane << 2)) = h;
}

// ---------------- kernel 2a: gather agg2 + GEMM1 -> g_emb ----------------
// 384 threads, 12 independent warp pipelines, 8 nodes per warp-group.
__global__ void __launch_bounds__(BT, 1)
k2a(const int* __restrict__ nodes, const int* __restrict__ n2,
    const float* __restrict__ W2g, int Nq, int numGroups) {
    extern __shared__ float sh[];
    float* W2s = sh;                       // 128*128 swizzled (64KB)
    float* xs  = W2s + 128 * 128;          // 96*128 node-major (48KB)

    int tid = threadIdx.x;
    for (int i = tid; i < 128 * 128; i += BT) {
        int r = i >> 7, k = i & 127;
        W2s[wswz(r, k)] = W2g[i];
    }
    __syncthreads();

    int lane = tid & 31;
    int wid  = tid >> 5;        // 0..11
    int jb   = wid << 3;        // this warp's 8 smem rows
    int rx7  = lane & 7;

    for (int grp = blockIdx.x * NWARP + wid; grp < numGroups; grp += gridDim.x * NWARP) {
        int base = grp << 3;

        // ---- gather agg2: 8 nodes, lane covers 16B of each 512B h1 row
#pragma unroll
        for (int s = 0; s < 8; s++) {
            int node = base + s;
            float4 acc = make_float4(0.f, 0.f, 0.f, 0.f);
            if (node < Nq) {
                int q = nodes[node];
                acc = *(const float4*)(g_h1 + (size_t)q * HID + (lane << 2));
                const int* nb = n2 + (size_t)q * S2;
#pragma unroll
                for (int jj = 0; jj < S2; jj++) {
                    int qq = nb[jj];
                    float4 u = *(const float4*)(g_h1 + (size_t)qq * HID + (lane << 2));
                    acc.x += u.x; acc.y += u.y; acc.z += u.z; acc.w += u.w;
                }
                const float inv = 1.f / (float)(S2 + 1);
                acc.x *= inv; acc.y *= inv; acc.z *= inv; acc.w *= inv;
            }
            *(float4*)(xs + (jb + s) * XP + (lane << 2)) = acc;
        }
        __syncwarp();

        // ---- GEMM1: emb = relu(W2 @ agg2) -> global, coalesced STG
        float v[4][8];
        const float init0[4] = {0.f, 0.f, 0.f, 0.f};
        gemmSw<4>(W2s + (lane << 7), xs + jb * XP, rx7, init0, v);
#pragma unroll
        for (int j = 0; j < 8; j++) {
            int node = base + j;
            if (node < Nq) {
#pragma unroll
                for (int ro = 0; ro < 4; ro++)
                    g_emb[(size_t)node * HID + lane + (ro << 5)] = fmaxf(v[ro][j], 0.f);
            }
        }
        __syncwarp();   // xs safe to overwrite next iteration
    }
}

// ---------------- kernel 2b: GEMM2 + GEMM3 + wc dot -> g_scores ----------------
__global__ void __launch_bounds__(BT, 1)
k2b(const float* __restrict__ wag, const float* __restrict__ bag,
    const float* __restrict__ wbg, const float* __restrict__ bbg,
    const float* __restrict__ wcg, const float* __restrict__ bcg,
    const int* __restrict__ psp, const int* __restrict__ nep,
    int Nq, int numGroups) {
    extern __shared__ float sh[];
    float* was = sh;                       // 128*128 swizzled (64KB)
    float* wbs = was + 128 * 128;          // 64*128 swizzled (32KB)
    float* xs  = wbs + 64 * 128;           // 96*128 (48KB)  emb in
    float* ys  = xs  + NWARP * 8 * XP;     // 96*128 (48KB)  ya
    float* waL = ys  + NWARP * 8 * XP;     // 128 (last col of w_a)
    float* wcs = waL + 128;                // 64
    float* bas = wcs + 64;                 // 128
    float* bbs = bas + 128;                // 64

    int tid = threadIdx.x;
    for (int i = tid; i < 128 * 129; i += BT) {
        int r = i / 129, k = i - r * 129;
        if (k < 128) was[wswz(r, k)] = wag[i]; else waL[r] = wag[i];
    }
    for (int i = tid; i < 64 * 128; i += BT) {
        int r = i >> 7, k = i & 127;
        wbs[wswz(r, k)] = wbg[i];
    }
    if (tid < 64)  wcs[tid] = wcg[tid];
    if (tid < 128) bas[tid] = bag[tid];
    if (tid < 64)  bbs[tid] = bbg[tid];
    float rem = (float)(psp[0] - nep[0]);
    float bcv = bcg[0];
    __syncthreads();

    int lane = tid & 31;
    int wid  = tid >> 5;
    int jb   = wid << 3;
    int rx7  = lane & 7;

    for (int grp = blockIdx.x * NWARP + wid; grp < numGroups; grp += gridDim.x * NWARP) {
        int base = grp << 3;

        // ---- load emb rows (coalesced 512B per node) into xs
#pragma unroll
        for (int s = 0; s < 8; s++) {
            int node = base + s;
            float4 u = make_float4(0.f, 0.f, 0.f, 0.f);
            if (node < Nq)
                u = *(const float4*)(g_emb + (size_t)node * HID + (lane << 2));
            *(float4*)(xs + (jb + s) * XP + (lane << 2)) = u;
        }
        __syncwarp();

        float v[4][8];

        // ---- GEMM2: ya = relu(w_a @ [emb; rem] + b_a) -> ys
        {
            float init[4];
#pragma unroll
            for (int ro = 0; ro < 4; ro++) {
                int r = lane + (ro << 5);
                init[ro] = bas[r] + waL[r] * rem;
            }
            gemmSw<4>(was + (lane << 7), xs + jb * XP, rx7, init, v);
#pragma unroll
            for (int ro = 0; ro < 4; ro++)
#pragma unroll
                for (int j = 0; j < 8; j++)
                    ys[(jb + j) * XP + lane + (ro << 5)] = fmaxf(v[ro][j], 0.f);
        }
        __syncwarp();

        // ---- GEMM3 (rows lane, lane+32 of w_b) + wc dot, in-warp reduction
        {
            const float init0[2] = {0.f, 0.f};
            float v3[2][8];
            gemmSw<2>(wbs + (lane << 7), ys + jb * XP, rx7, init0, v3);
            float wc0 = wcs[lane],      bb0 = bbs[lane];
            float wc1 = wcs[lane + 32], bb1 = bbs[lane + 32];
            float c[8];
#pragma unroll
            for (int j = 0; j < 8; j++)
                c[j] = wc0 * fmaxf(v3[0][j] + bb0, 0.f)
                     + wc1 * fmaxf(v3[1][j] + bb1, 0.f);
#pragma unroll
            for (int off = 16; off; off >>= 1)
#pragma unroll
                for (int j = 0; j < 8; j++)
                    c[j] += __shfl_xor_sync(0xffffffffu, c[j], off);
            if (lane == 0) {
#pragma unroll
                for (int j = 0; j < 8; j++) {
                    int node = base + j;
                    if (node < Nq) g_scores[node] = c[j] + bcv;
                }
            }
        }
        __syncwarp();
    }
}

// ---------------- softmax (online max+sumexp) ----------------
__device__ __forceinline__ void sm_comb(float& m, float& s, float mo, float so) {
    if (mo > m) { float t = m; m = mo; mo = t; t = s; s = so; so = t; }
    if (so != 0.f) s += so * expf(mo - m);
}

__global__ void k_red1(int N) {
    float m = -FLT_MAX, s = 0.f;
    for (int i = blockIdx.x * blockDim.x + threadIdx.x; i < N; i += gridDim.x * blockDim.x) {
        float x = g_scores[i];
        if (x > m) { s = s * expf(m - x) + 1.f; m = x; }
        else        s += expf(x - m);
    }
#pragma unroll
    for (int off = 16; off; off >>= 1) {
        float mo = __shfl_xor_sync(0xffffffffu, m, off);
        float so = __shfl_xor_sync(0xffffffffu, s, off);
        sm_comb(m, s, mo, so);
    }
    __shared__ float shm[8], shs[8];
    int lane = threadIdx.x & 31, wid = threadIdx.x >> 5;
    if (lane == 0) { shm[wid] = m; shs[wid] = s; }
    __syncthreads();
    if (threadIdx.x < 32) {
        float m2 = (lane < 8) ? shm[lane] : -FLT_MAX;
        float s2 = (lane < 8) ? shs[lane] : 0.f;
#pragma unroll
        for (int off = 4; off; off >>= 1) {
            float mo = __shfl_xor_sync(0xffffffffu, m2, off);
            float so = __shfl_xor_sync(0xffffffffu, s2, off);
            sm_comb(m2, s2, mo, so);
        }
        if (threadIdx.x == 0) { g_pm[blockIdx.x] = m2; g_ps[blockIdx.x] = s2; }
    }
}

__global__ void k_red2(int RB) {
    int t = threadIdx.x;
    float m = (t < RB) ? g_pm[t] : -FLT_MAX;
    float s = (t < RB) ? g_ps[t] : 0.f;
#pragma unroll
    for (int off = 16; off; off >>= 1) {
        float mo = __shfl_xor_sync(0xffffffffu, m, off);
        float so = __shfl_xor_sync(0xffffffffu, s, off);
        sm_comb(m, s, mo, so);
    }
    __shared__ float shm[8], shs[8];
    int lane = t & 31, wid = t >> 5;
    if (lane == 0) { shm[wid] = m; shs[wid] = s; }
    __syncthreads();
    if (t < 32) {
        float m2 = (lane < 8) ? shm[lane] : -FLT_MAX;
        float s2 = (lane < 8) ? shs[lane] : 0.f;
#pragma unroll
        for (int off = 4; off; off >>= 1) {
            float mo = __shfl_xor_sync(0xffffffffu, m2, off);
            float so = __shfl_xor_sync(0xffffffffu, s2, off);
            sm_comb(m2, s2, mo, so);
        }
        if (t == 0) { g_MS[0] = m2; g_MS[1] = 1.f / s2; }
    }
}

__global__ void k_norm(float* __restrict__ out, int N) {
    int i = blockIdx.x * blockDim.x + threadIdx.x;
    if (i < N) out[i] = expf(g_scores[i] - g_MS[0]) * g_MS[1];
}

// ---------------- launch ----------------
static const int SMEM2A = (128 * 128 + NWARP * 8 * XP) * (int)sizeof(float);
static const int SMEM2B = (128 * 128 + 64 * 128 + 2 * NWARP * 8 * XP
                           + 128 + 64 + 128 + 64) * (int)sizeof(float);

extern "C" void kernel_launch(void* const* d_in, const int* in_sizes, int n_in,
                              void* d_out, int out_size) {
    const int*   nodes = (const int*)d_in[0];
    const float* feat  = (const float*)d_in[1];
    const int*   n1    = (const int*)d_in[2];
    const int*   n2    = (const int*)d_in[3];
    const float* W1    = (const float*)d_in[4];
    const float* W2    = (const float*)d_in[5];
    const float* wa    = (const float*)d_in[6];
    const float* ba    = (const float*)d_in[7];
    const float* wb    = (const float*)d_in[8];
    const float* bb    = (const float*)d_in[9];
    const float* wc    = (const float*)d_in[10];
    const float* bc    = (const float*)d_in[11];
    const int*   ps    = (const int*)d_in[12];
    const int*   ne    = (const int*)d_in[13];

    int Nq = in_sizes[0];
    int NN = in_sizes[1] / 3;

    cudaFuncSetAttribute(k2a, cudaFuncAttributeMaxDynamicSharedMemorySize, SMEM2A);
    cudaFuncSetAttribute(k2b, cudaFuncAttributeMaxDynamicSharedMemorySize, SMEM2B);

    k_pad<<<(NN + 255) / 256, 256>>>(feat, NN);
    k_enc1<<<(NN + 7) / 8, 256>>>(n1, W1, NN);

    int numGroups = (Nq + 7) / 8;
    k2a<<<152, BT, SMEM2A>>>(nodes, n2, W2, Nq, numGroups);
    k2b<<<152, BT, SMEM2B>>>(wa, ba, wb, bb, wc, bc, ps, ne, Nq, numGroups);

    k_red1<<<240, 256>>>(Nq);
    k_red2<<<1, 256>>>(240);
    k_norm<<<(Nq + 255) / 256, 256>>>((float*)d_out, Nq);
}